// round 3
// baseline (speedup 1.0000x reference)
#include <cuda_runtime.h>

#define BB 32
#define DD 512
#define KK 64
#define NNN 1024

#define NT1 128   // K1 n-tile
#define DT  16    // K1 d-chunk
#define NT2 16    // K2 n-chunk

// Scratch (allocation-free rule: __device__ globals)
__device__ __align__(16) float g_assign[(size_t)BB * KK * NNN];   // 8 MB
__device__ __align__(16) float g_vlad2[2][(size_t)BB * DD * KK];  // 2 x 4 MB

typedef unsigned long long u64;

__device__ __forceinline__ void fma2(u64 &d, u64 a, u64 b) {
    asm("fma.rn.f32x2 %0, %1, %2, %0;" : "+l"(d) : "l"(a), "l"(b));
}
__device__ __forceinline__ float2 unpack2(u64 v) {
    float2 r;
    asm("mov.b64 {%0, %1}, %2;" : "=f"(r.x), "=f"(r.y) : "l"(v));
    return r;
}

// ---------------------------------------------------------------------------
// K1: scores = W @ x  (64k x 128n tile per block), double-buffered smem,
//     fused softmax over K, writes assign[b,k,n].
// Thread: 8 contiguous k (8*tyk..) x 4 contiguous n (4*txn..).
// ---------------------------------------------------------------------------
__global__ void __launch_bounds__(256, 2)
k1_scores_softmax(const float* __restrict__ x, const float* __restrict__ w) {
    // 32 KB: Wdup[2][DT][KK] float2 (16KB) + Xs[2][DT][NT1] float (16KB);
    // softmax overlays the whole thing as Ss[KK][NT1] (32KB).
    __shared__ __align__(16) char smraw[32 * 1024];
    float2 (*Wdup)[DT][KK] = reinterpret_cast<float2(*)[DT][KK]>(smraw);
    float  (*Xs)[DT][NT1]  = reinterpret_cast<float(*)[DT][NT1]>(smraw + 16 * 1024);
    float  (*Ss)[NT1]      = reinterpret_cast<float(*)[NT1]>(smraw);

    const int b   = blockIdx.y;
    const int n0  = blockIdx.x * NT1;
    const int tid = threadIdx.x;
    const int txn = tid & 31;   // n = 4*txn + {0..3}
    const int tyk = tid >> 5;   // k = 8*tyk + {0..7}

    const float* xb = x + (size_t)b * DD * NNN;

    u64 acc[8][2];
#pragma unroll
    for (int i = 0; i < 8; i++) { acc[i][0] = 0ull; acc[i][1] = 0ull; }

    // loader roles
    const int wk   = tid >> 2;         // 0..63
    const int wd4  = (tid & 3) << 2;   // 0,4,8,12
    const int xrow = tid >> 5;         // 0..7
    const int xcol = (tid & 31) << 2;  // 0..124

    float4 wv, xv0, xv1;
    // prologue: chunk 0 -> regs -> buf 0
    wv  = *reinterpret_cast<const float4*>(w  + (size_t)wk * DD + wd4);
    xv0 = *reinterpret_cast<const float4*>(xb + (size_t)xrow * NNN + n0 + xcol);
    xv1 = *reinterpret_cast<const float4*>(xb + (size_t)(xrow + 8) * NNN + n0 + xcol);
    Wdup[0][wd4 + 0][wk] = make_float2(wv.x, wv.x);
    Wdup[0][wd4 + 1][wk] = make_float2(wv.y, wv.y);
    Wdup[0][wd4 + 2][wk] = make_float2(wv.z, wv.z);
    Wdup[0][wd4 + 3][wk] = make_float2(wv.w, wv.w);
    *reinterpret_cast<float4*>(&Xs[0][xrow][xcol])     = xv0;
    *reinterpret_cast<float4*>(&Xs[0][xrow + 8][xcol]) = xv1;
    __syncthreads();

    const int NCHUNK = DD / DT;  // 32
    for (int c = 0; c < NCHUNK; c++) {
        const int cur = c & 1, nxt = cur ^ 1;
        const int dt1 = (c + 1) * DT;
        if (dt1 < DD) {  // prefetch next chunk into registers
            wv  = *reinterpret_cast<const float4*>(w  + (size_t)wk * DD + dt1 + wd4);
            xv0 = *reinterpret_cast<const float4*>(xb + (size_t)(dt1 + xrow) * NNN + n0 + xcol);
            xv1 = *reinterpret_cast<const float4*>(xb + (size_t)(dt1 + xrow + 8) * NNN + n0 + xcol);
        }
#pragma unroll
        for (int dd = 0; dd < DT; dd++) {
            float4 xq = *reinterpret_cast<const float4*>(&Xs[cur][dd][4 * txn]);  // LDS.128, conflict-free
            u64 xp0 = reinterpret_cast<const u64*>(&xq)[0];
            u64 xp1 = reinterpret_cast<const u64*>(&xq)[1];
#pragma unroll
            for (int j = 0; j < 4; j++) {
                float4 wq = *reinterpret_cast<const float4*>(&Wdup[cur][dd][8 * tyk + 2 * j]);  // LDS.128 broadcast
                u64 wp0 = reinterpret_cast<const u64*>(&wq)[0];
                u64 wp1 = reinterpret_cast<const u64*>(&wq)[1];
                fma2(acc[2 * j + 0][0], wp0, xp0);
                fma2(acc[2 * j + 0][1], wp0, xp1);
                fma2(acc[2 * j + 1][0], wp1, xp0);
                fma2(acc[2 * j + 1][1], wp1, xp1);
            }
        }
        if (dt1 < DD) {  // stage prefetched regs into the other buffer
            Wdup[nxt][wd4 + 0][wk] = make_float2(wv.x, wv.x);
            Wdup[nxt][wd4 + 1][wk] = make_float2(wv.y, wv.y);
            Wdup[nxt][wd4 + 2][wk] = make_float2(wv.z, wv.z);
            Wdup[nxt][wd4 + 3][wk] = make_float2(wv.w, wv.w);
            *reinterpret_cast<float4*>(&Xs[nxt][xrow][xcol])     = xv0;
            *reinterpret_cast<float4*>(&Xs[nxt][xrow + 8][xcol]) = xv1;
        }
        __syncthreads();
    }

    // scores -> Ss overlay (safe: loop ended with a sync)
#pragma unroll
    for (int i = 0; i < 8; i++) {
        float2 a0 = unpack2(acc[i][0]);
        float2 a1 = unpack2(acc[i][1]);
        *reinterpret_cast<float4*>(&Ss[8 * tyk + i][4 * txn]) =
            make_float4(a0.x, a0.y, a1.x, a1.y);
    }
    __syncthreads();

    // softmax over K per column
    if (tid < NT1) {
        const int c = tid;
        float mx = -1e30f;
#pragma unroll
        for (int k = 0; k < KK; k++) mx = fmaxf(mx, Ss[k][c]);
        float s = 0.f;
#pragma unroll
        for (int k = 0; k < KK; k++) {
            float e = __expf(Ss[k][c] - mx);
            Ss[k][c] = e;
            s += e;
        }
        float is = 1.f / s;
        float* ab = g_assign + (size_t)b * KK * NNN + n0 + c;
#pragma unroll
        for (int k = 0; k < KK; k++) ab[(size_t)k * NNN] = Ss[k][c] * is;
    }
}

// ---------------------------------------------------------------------------
// K2: partial vlad over an n-half (z = 0/1):
//     g_vlad2[z][b, d0:d0+128, :] = sum_{n in half} x*assign - centers*asum_half
// Thread: 8 contiguous d (8*tyd..) x 4 contiguous k (4*tx..).
// ---------------------------------------------------------------------------
__global__ void __launch_bounds__(256, 2)
k2_vlad(const float* __restrict__ x, const float* __restrict__ centers) {
    __shared__ __align__(16) float2 Xd[2][NT2][128];  // 2 x 16 KB, duplicated pairs
    __shared__ __align__(16) float  As[2][NT2][KK];   // 2 x 4 KB
    __shared__ float asums[KK];

    const int b   = blockIdx.y;
    const int d0  = blockIdx.x * 128;
    const int z   = blockIdx.z;
    const int nb  = z * (NNN / 2);    // 512-wide half
    const int tid = threadIdx.x;
    const int tx  = tid & 15;   // k = 4*tx + {0..3}
    const int tyd = tid >> 4;   // d = d0 + 8*tyd + {0..7}

    const float* xb = x + (size_t)b * DD * NNN;
    const float* ab = g_assign + (size_t)b * KK * NNN;

    u64 acc[8][2];
#pragma unroll
    for (int i = 0; i < 8; i++) { acc[i][0] = 0ull; acc[i][1] = 0ull; }
    float asum = 0.f;

    // loader roles
    const int xd  = tid >> 1;          // 0..127
    const int xnb = (tid & 1) * 8;     // 0 or 8
    const int ak  = tid & 63;          // 0..63
    const int anb = (tid >> 6) * 4;    // 0,4,8,12

    float4 xv0, xv1, av;
    xv0 = *reinterpret_cast<const float4*>(xb + (size_t)(d0 + xd) * NNN + nb + xnb);
    xv1 = *reinterpret_cast<const float4*>(xb + (size_t)(d0 + xd) * NNN + nb + xnb + 4);
    av  = *reinterpret_cast<const float4*>(ab + (size_t)ak * NNN + nb + anb);
    Xd[0][xnb + 0][xd] = make_float2(xv0.x, xv0.x);
    Xd[0][xnb + 1][xd] = make_float2(xv0.y, xv0.y);
    Xd[0][xnb + 2][xd] = make_float2(xv0.z, xv0.z);
    Xd[0][xnb + 3][xd] = make_float2(xv0.w, xv0.w);
    Xd[0][xnb + 4][xd] = make_float2(xv1.x, xv1.x);
    Xd[0][xnb + 5][xd] = make_float2(xv1.y, xv1.y);
    Xd[0][xnb + 6][xd] = make_float2(xv1.z, xv1.z);
    Xd[0][xnb + 7][xd] = make_float2(xv1.w, xv1.w);
    As[0][anb + 0][ak] = av.x;
    As[0][anb + 1][ak] = av.y;
    As[0][anb + 2][ak] = av.z;
    As[0][anb + 3][ak] = av.w;
    __syncthreads();

    const int NCHUNK = (NNN / 2) / NT2;  // 32
    for (int c = 0; c < NCHUNK; c++) {
        const int cur = c & 1, nxt = cur ^ 1;
        const int n1 = nb + (c + 1) * NT2;
        if (c + 1 < NCHUNK) {
            xv0 = *reinterpret_cast<const float4*>(xb + (size_t)(d0 + xd) * NNN + n1 + xnb);
            xv1 = *reinterpret_cast<const float4*>(xb + (size_t)(d0 + xd) * NNN + n1 + xnb + 4);
            av  = *reinterpret_cast<const float4*>(ab + (size_t)ak * NNN + n1 + anb);
        }
        if (tid < KK) {
            float s = 0.f;
#pragma unroll
            for (int nn = 0; nn < NT2; nn++) s += As[cur][nn][tid];
            asum += s;
        }
#pragma unroll
        for (int nn = 0; nn < NT2; nn++) {
            float4 aq = *reinterpret_cast<const float4*>(&As[cur][nn][4 * tx]);  // LDS.128
            u64 ap0 = reinterpret_cast<const u64*>(&aq)[0];
            u64 ap1 = reinterpret_cast<const u64*>(&aq)[1];
#pragma unroll
            for (int i2 = 0; i2 < 4; i2++) {
                float4 xq = *reinterpret_cast<const float4*>(&Xd[cur][nn][8 * tyd + 2 * i2]);  // LDS.128 (2 dup pairs)
                u64 xp0 = reinterpret_cast<const u64*>(&xq)[0];
                u64 xp1 = reinterpret_cast<const u64*>(&xq)[1];
                fma2(acc[2 * i2 + 0][0], xp0, ap0);
                fma2(acc[2 * i2 + 0][1], xp0, ap1);
                fma2(acc[2 * i2 + 1][0], xp1, ap0);
                fma2(acc[2 * i2 + 1][1], xp1, ap1);
            }
        }
        if (c + 1 < NCHUNK) {
            Xd[nxt][xnb + 0][xd] = make_float2(xv0.x, xv0.x);
            Xd[nxt][xnb + 1][xd] = make_float2(xv0.y, xv0.y);
            Xd[nxt][xnb + 2][xd] = make_float2(xv0.z, xv0.z);
            Xd[nxt][xnb + 3][xd] = make_float2(xv0.w, xv0.w);
            Xd[nxt][xnb + 4][xd] = make_float2(xv1.x, xv1.x);
            Xd[nxt][xnb + 5][xd] = make_float2(xv1.y, xv1.y);
            Xd[nxt][xnb + 6][xd] = make_float2(xv1.z, xv1.z);
            Xd[nxt][xnb + 7][xd] = make_float2(xv1.w, xv1.w);
            As[nxt][anb + 0][ak] = av.x;
            As[nxt][anb + 1][ak] = av.y;
            As[nxt][anb + 2][ak] = av.z;
            As[nxt][anb + 3][ak] = av.w;
        }
        __syncthreads();
    }

    if (tid < KK) asums[tid] = asum;   // partial asum for this half
    __syncthreads();

    // epilogue: subtract centers * asum_half (linear, halves sum correctly)
    float* vz = g_vlad2[z];
#pragma unroll
    for (int i = 0; i < 8; i++) {
        int d = d0 + 8 * tyd + i;
#pragma unroll
        for (int p = 0; p < 2; p++) {
            int k0 = 4 * tx + 2 * p;
            float2 a  = unpack2(acc[i][p]);
            float2 cv = *reinterpret_cast<const float2*>(centers + (size_t)d * KK + k0);
            float2 o  = make_float2(a.x - cv.x * asums[k0],
                                    a.y - cv.y * asums[k0 + 1]);
            *reinterpret_cast<float2*>(vz + ((size_t)b * DD + d) * KK + k0) = o;
        }
    }
}

// ---------------------------------------------------------------------------
// K3: combine halves, intra-normalize over D per (b,k), global L2 normalize.
// ---------------------------------------------------------------------------
__global__ void __launch_bounds__(256)
k3_normalize(float* __restrict__ out) {
    const int b   = blockIdx.x;
    const int tid = threadIdx.x;
    const int k   = tid & 63;
    const int ds  = tid >> 6;  // 0..3

    const float* v0 = g_vlad2[0] + (size_t)b * DD * KK;
    const float* v1 = g_vlad2[1] + (size_t)b * DD * KK;

    float ss = 0.f;
    for (int d = ds; d < DD; d += 4) {
        float v = v0[(size_t)d * KK + k] + v1[(size_t)d * KK + k];
        ss = fmaf(v, v, ss);
    }

    __shared__ float red[4][KK];
    __shared__ float invk[KK];
    __shared__ float ginv;

    red[ds][k] = ss;
    __syncthreads();
    if (tid < KK) {
        float t = red[0][tid] + red[1][tid] + red[2][tid] + red[3][tid];
        float nrm = fmaxf(sqrtf(t), 1e-12f);
        float iv = 1.f / nrm;
        invk[tid] = iv;
        red[0][tid] = t * iv * iv;
    }
    __syncthreads();
    if (tid == 0) {
        float g = 0.f;
        for (int i = 0; i < KK; i++) g += red[0][i];
        ginv = 1.f / fmaxf(sqrtf(g), 1e-12f);
    }
    __syncthreads();

    const float gi = ginv;
    float* ob = out + (size_t)b * DD * KK;
    for (int d = ds; d < DD; d += 4) {
        float v = v0[(size_t)d * KK + k] + v1[(size_t)d * KK + k];
        ob[(size_t)d * KK + k] = v * invk[k] * gi;
    }
}

// ---------------------------------------------------------------------------
extern "C" void kernel_launch(void* const* d_in, const int* in_sizes, int n_in,
                              void* d_out, int out_size) {
    const float* x       = (const float*)d_in[0];  // [32,512,1024]
    const float* conv_w  = (const float*)d_in[1];  // [64,512]
    const float* centers = (const float*)d_in[2];  // [512,64]
    float* out = (float*)d_out;                    // [32, 512*64]

    k1_scores_softmax<<<dim3(NNN / NT1, BB), 256>>>(x, conv_w);
    k2_vlad<<<dim3(DD / 128, BB, 2), 256>>>(x, centers);
    k3_normalize<<<BB, 256>>>(out);
}

// round 5
// speedup vs baseline: 1.7502x; 1.7502x over previous
#include <cuda_runtime.h>
#include <cuda_bf16.h>

#define BB 32
#define DD 512
#define KK 64
#define NNN 1024
#define STW 20   // smem row stride in 4B words (= 40 bf16 elements)

typedef unsigned int u32;

// Scratch (__device__ globals; allocation-free rule)
__device__ __align__(16) __nv_bfloat16 g_assign_hi[(size_t)BB * KK * NNN]; // 4 MB
__device__ __align__(16) __nv_bfloat16 g_assign_lo[(size_t)BB * KK * NNN]; // 4 MB
__device__ __align__(16) float g_asum_part[(size_t)BB * 8 * KK];
__device__ __align__(16) float g_vlad[(size_t)BB * DD * KK];               // 4 MB

// ---------------- helpers ----------------
__device__ __forceinline__ u32 pack_bf2(float a, float b) {
    __nv_bfloat162 p(__float2bfloat16_rn(a), __float2bfloat16_rn(b));
    return *reinterpret_cast<u32*>(&p);
}
__device__ __forceinline__ u32 split_pack(float a, float b, float& la, float& lb) {
    __nv_bfloat16 ha = __float2bfloat16_rn(a);
    __nv_bfloat16 hb = __float2bfloat16_rn(b);
    la = a - __bfloat162float(ha);
    lb = b - __bfloat162float(hb);
    __nv_bfloat162 p(ha, hb);
    return *reinterpret_cast<u32*>(&p);
}
__device__ __forceinline__ void mma16816(float* c, u32 a0, u32 a1, u32 a2, u32 a3,
                                         u32 b0, u32 b1) {
    asm volatile(
        "mma.sync.aligned.m16n8k16.row.col.f32.bf16.bf16.f32 "
        "{%0,%1,%2,%3},{%4,%5,%6,%7},{%8,%9},{%0,%1,%2,%3};"
        : "+f"(c[0]), "+f"(c[1]), "+f"(c[2]), "+f"(c[3])
        : "r"(a0), "r"(a1), "r"(a2), "r"(a3), "r"(b0), "r"(b1));
}

// ---------------------------------------------------------------------------
// K1: D[n=128, k=64] = x^T W^T (3-MMA bf16 split), fused softmax over k,
//     writes assign hi/lo bf16 planes (k-major) + per-tile asum partials.
// Grid (8, 32). Dyn smem (words): A [buf][plane][128*20] at 0 (10240 words),
// W [buf][plane][64*20] at 10240 (5120 words). Score overlay f32[128][65].
// ---------------------------------------------------------------------------
__global__ void __launch_bounds__(256, 2)
k1_scores(const float* __restrict__ x, const float* __restrict__ w) {
    extern __shared__ __align__(16) char dyn[];
    u32*   sm  = reinterpret_cast<u32*>(dyn);
    float* smf = reinterpret_cast<float*>(dyn);

    const int tid = threadIdx.x;
    const int b   = blockIdx.y;
    const int n0  = blockIdx.x * 128;
    const float* xb = x + (size_t)b * DD * NNN;

    const int lane = tid & 31, g = lane >> 2, tig = lane & 3;
    const int wid = tid >> 5, wm = wid >> 1, wn = wid & 1;

    // staging roles
    const int p  = tid & 15;        // A: d-pair index (rows 2p, 2p+1 of chunk)
    const int ng = tid >> 4;        // A: n8 = ng*8
    const int wr = tid >> 2;        // W: k row 0..63
    const int d8 = (tid & 3) * 8;   // W: d offset in chunk

    float c[2][4][4];
#pragma unroll
    for (int i = 0; i < 2; i++)
#pragma unroll
        for (int j = 0; j < 4; j++)
#pragma unroll
            for (int q = 0; q < 4; q++) c[i][j][q] = 0.f;

    float4 xa0, xa1, xc0, xc1, wv0, wv1;

    auto loadChunk = [&](int dc) {
        const float* r0 = xb + (size_t)(dc + 2 * p) * NNN + n0 + ng * 8;
        xa0 = *(const float4*)r0;
        xa1 = *(const float4*)(r0 + 4);
        const float* r1 = r0 + NNN;
        xc0 = *(const float4*)r1;
        xc1 = *(const float4*)(r1 + 4);
        const float* wp = w + (size_t)wr * DD + dc + d8;
        wv0 = *(const float4*)wp;
        wv1 = *(const float4*)(wp + 4);
    };
    auto storeChunk = [&](int buf) {
        // A (transpose): word(n, p) = pack(x[2p][n], x[2p+1][n])
        float f0[8] = {xa0.x, xa0.y, xa0.z, xa0.w, xa1.x, xa1.y, xa1.z, xa1.w};
        float f1[8] = {xc0.x, xc0.y, xc0.z, xc0.w, xc1.x, xc1.y, xc1.z, xc1.w};
        const u32 Ah = buf * 5120u, Al = Ah + 2560u;
#pragma unroll
        for (int j = 0; j < 8; j++) {
            const int n = ng * 8 + j;
            float la, lb;
            u32 hi = split_pack(f0[j], f1[j], la, lb);
            u32 lo = pack_bf2(la, lb);
            sm[Ah + (u32)n * STW + p] = hi;
            sm[Al + (u32)n * STW + p] = lo;
        }
        // W: row k, 8 d values -> 4 words, 16B-aligned vec4 store
        float f[8] = {wv0.x, wv0.y, wv0.z, wv0.w, wv1.x, wv1.y, wv1.z, wv1.w};
        u32 hw[4], lw[4];
#pragma unroll
        for (int j = 0; j < 4; j++) {
            float la, lb;
            hw[j] = split_pack(f[2 * j], f[2 * j + 1], la, lb);
            lw[j] = pack_bf2(la, lb);
        }
        const u32 Wh = 10240u + buf * 2560u, Wl = Wh + 1280u;
        *(uint4*)&sm[Wh + (u32)wr * STW + (d8 >> 1)] = make_uint4(hw[0], hw[1], hw[2], hw[3]);
        *(uint4*)&sm[Wl + (u32)wr * STW + (d8 >> 1)] = make_uint4(lw[0], lw[1], lw[2], lw[3]);
    };

    loadChunk(0);
    storeChunk(0);
    __syncthreads();

    for (int ch = 0; ch < 16; ch++) {
        const int buf = ch & 1;
        if (ch < 15) loadChunk((ch + 1) * 32);

        const u32 Ah = buf * 5120u, Al = Ah + 2560u;
        const u32 Wh = 10240u + buf * 2560u, Wl = Wh + 1280u;
#pragma unroll
        for (int ks = 0; ks < 2; ks++) {
            u32 bh0[4], bh1[4], bl0[4], bl1[4];
#pragma unroll
            for (int nt = 0; nt < 4; nt++) {
                const u32 wB = (u32)(wn * 32 + nt * 8 + g) * STW + ks * 8 + tig;
                bh0[nt] = sm[Wh + wB];
                bh1[nt] = sm[Wh + wB + 4];
                bl0[nt] = sm[Wl + wB];
                bl1[nt] = sm[Wl + wB + 4];
            }
#pragma unroll
            for (int mt = 0; mt < 2; mt++) {
                const u32 wA = (u32)(wm * 32 + mt * 16 + g) * STW + ks * 8 + tig;
                u32 ah0 = sm[Ah + wA], ah1 = sm[Ah + wA + 8 * STW];
                u32 ah2 = sm[Ah + wA + 4], ah3 = sm[Ah + wA + 8 * STW + 4];
                u32 al0 = sm[Al + wA], al1 = sm[Al + wA + 8 * STW];
                u32 al2 = sm[Al + wA + 4], al3 = sm[Al + wA + 8 * STW + 4];
#pragma unroll
                for (int nt = 0; nt < 4; nt++) {
                    mma16816(c[mt][nt], ah0, ah1, ah2, ah3, bh0[nt], bh1[nt]);
                    mma16816(c[mt][nt], ah0, ah1, ah2, ah3, bl0[nt], bl1[nt]);
                    mma16816(c[mt][nt], al0, al1, al2, al3, bh0[nt], bh1[nt]);
                }
            }
        }
        if (ch < 15) storeChunk(buf ^ 1);
        __syncthreads();
    }

    // scores -> smem overlay [128][65] f32
#pragma unroll
    for (int mt = 0; mt < 2; mt++) {
        const int r0 = wm * 32 + mt * 16 + g;
#pragma unroll
        for (int nt = 0; nt < 4; nt++) {
            const int col = wn * 32 + nt * 8 + 2 * tig;
            smf[r0 * 65 + col]           = c[mt][nt][0];
            smf[r0 * 65 + col + 1]       = c[mt][nt][1];
            smf[(r0 + 8) * 65 + col]     = c[mt][nt][2];
            smf[(r0 + 8) * 65 + col + 1] = c[mt][nt][3];
        }
    }
    __syncthreads();

    // softmax over k per n-row
    if (tid < 128) {
        float r[64];
#pragma unroll
        for (int i = 0; i < 64; i++) r[i] = smf[tid * 65 + i];
        float mx = r[0];
#pragma unroll
        for (int i = 1; i < 64; i++) mx = fmaxf(mx, r[i]);
        float s = 0.f;
#pragma unroll
        for (int i = 0; i < 64; i++) { r[i] = __expf(r[i] - mx); s += r[i]; }
        const float is = 1.f / s;
#pragma unroll
        for (int i = 0; i < 64; i++) smf[tid * 65 + i] = r[i] * is;
    }
    __syncthreads();

    if (tid < 64) {  // asum partial for this tile
        float s = 0.f;
        for (int rw = 0; rw < 128; rw++) s += smf[rw * 65 + tid];
        g_asum_part[((size_t)b * 8 + blockIdx.x) * KK + tid] = s;
    }
    {   // assign -> bf16 hi/lo planes, k-major
        const int k  = tid >> 2;
        const int ns = (tid & 3) * 32;
        __nv_bfloat16* oh = g_assign_hi + ((size_t)b * KK + k) * NNN + n0 + ns;
        __nv_bfloat16* ol = g_assign_lo + ((size_t)b * KK + k) * NNN + n0 + ns;
#pragma unroll
        for (int j = 0; j < 32; j += 2) {
            float a0 = smf[(ns + j) * 65 + k];
            float a1 = smf[(ns + j + 1) * 65 + k];
            float la, lb;
            u32 hp = split_pack(a0, a1, la, lb);
            u32 lp = pack_bf2(la, lb);
            *reinterpret_cast<u32*>(oh + j) = hp;
            *reinterpret_cast<u32*>(ol + j) = lp;
        }
    }
}

// ---------------------------------------------------------------------------
// K2: D[d=64, k=64] = x · assign^T over n=1024 (3-MMA split), fused
//     "- centers * asum" epilogue. Grid (8, 32).
// Dyn smem (words): A [buf][plane][64*20] at 0 (5120), B same at 5120.
// ---------------------------------------------------------------------------
__global__ void __launch_bounds__(256, 2)
k2_vlad(const float* __restrict__ x, const float* __restrict__ centers) {
    extern __shared__ __align__(16) char dyn[];
    u32* sm = reinterpret_cast<u32*>(dyn);
    __shared__ float s_asum[KK];

    const int tid = threadIdx.x;
    const int b   = blockIdx.y;
    const int d0  = blockIdx.x * 64;

    const int lane = tid & 31, g = lane >> 2, tig = lane & 3;
    const int wid = tid >> 5, wm = wid >> 1, wn = wid & 1;

    const int rr = tid >> 2;        // staging row (d for A, k for B)
    const int n8 = (tid & 3) * 8;

    if (tid < 64) {
        float s = 0.f;
#pragma unroll
        for (int q = 0; q < 8; q++) s += g_asum_part[((size_t)b * 8 + q) * KK + tid];
        s_asum[tid] = s;
    }

    const float* xb = x + (size_t)b * DD * NNN;
    const __nv_bfloat16* ah = g_assign_hi + ((size_t)b * KK + rr) * NNN;
    const __nv_bfloat16* al = g_assign_lo + ((size_t)b * KK + rr) * NNN;

    float c[4][4];
#pragma unroll
    for (int j = 0; j < 4; j++)
#pragma unroll
        for (int q = 0; q < 4; q++) c[j][q] = 0.f;

    float4 xv0, xv1;
    uint4 bh4, bl4;

    auto loadChunk = [&](int nb) {
        const float* xp = xb + (size_t)(d0 + rr) * NNN + nb + n8;
        xv0 = *(const float4*)xp;
        xv1 = *(const float4*)(xp + 4);
        bh4 = *(const uint4*)(ah + nb + n8);
        bl4 = *(const uint4*)(al + nb + n8);
    };
    auto storeChunk = [&](int buf) {
        float f[8] = {xv0.x, xv0.y, xv0.z, xv0.w, xv1.x, xv1.y, xv1.z, xv1.w};
        u32 hw[4], lw[4];
#pragma unroll
        for (int j = 0; j < 4; j++) {
            float la, lb;
            hw[j] = split_pack(f[2 * j], f[2 * j + 1], la, lb);
            lw[j] = pack_bf2(la, lb);
        }
        const u32 Ahh = buf * 2560u, All = Ahh + 1280u;
        *(uint4*)&sm[Ahh + (u32)rr * STW + (n8 >> 1)] = make_uint4(hw[0], hw[1], hw[2], hw[3]);
        *(uint4*)&sm[All + (u32)rr * STW + (n8 >> 1)] = make_uint4(lw[0], lw[1], lw[2], lw[3]);
        const u32 Bh = 5120u + buf * 2560u, Bl = Bh + 1280u;
        *(uint4*)&sm[Bh + (u32)rr * STW + (n8 >> 1)] = bh4;
        *(uint4*)&sm[Bl + (u32)rr * STW + (n8 >> 1)] = bl4;
    };

    loadChunk(0);
    storeChunk(0);
    __syncthreads();

    for (int ch = 0; ch < 32; ch++) {
        const int buf = ch & 1;
        if (ch < 31) loadChunk((ch + 1) * 32);

        const u32 Ahh = buf * 2560u, All = Ahh + 1280u;
        const u32 Bh = 5120u + buf * 2560u, Bl = Bh + 1280u;
#pragma unroll
        for (int ks = 0; ks < 2; ks++) {
            u32 bh0[4], bh1[4], bl0[4], bl1[4];
#pragma unroll
            for (int nt = 0; nt < 4; nt++) {
                const u32 wB = (u32)(wn * 32 + nt * 8 + g) * STW + ks * 8 + tig;
                bh0[nt] = sm[Bh + wB];
                bh1[nt] = sm[Bh + wB + 4];
                bl0[nt] = sm[Bl + wB];
                bl1[nt] = sm[Bl + wB + 4];
            }
            const u32 wA = (u32)(wm * 16 + g) * STW + ks * 8 + tig;
            u32 ah0 = sm[Ahh + wA], ah1 = sm[Ahh + wA + 8 * STW];
            u32 ah2 = sm[Ahh + wA + 4], ah3 = sm[Ahh + wA + 8 * STW + 4];
            u32 al0 = sm[All + wA], al1 = sm[All + wA + 8 * STW];
            u32 al2 = sm[All + wA + 4], al3 = sm[All + wA + 8 * STW + 4];
#pragma unroll
            for (int nt = 0; nt < 4; nt++) {
                mma16816(c[nt], ah0, ah1, ah2, ah3, bh0[nt], bh1[nt]);
                mma16816(c[nt], ah0, ah1, ah2, ah3, bl0[nt], bl1[nt]);
                mma16816(c[nt], al0, al1, al2, al3, bh0[nt], bh1[nt]);
            }
        }
        if (ch < 31) storeChunk(buf ^ 1);
        __syncthreads();
    }

    // epilogue: vlad[d][k] = D - centers[d][k] * asum[k]
    const int dr0 = d0 + wm * 16 + g;
    const int dr1 = dr0 + 8;
#pragma unroll
    for (int nt = 0; nt < 4; nt++) {
        const int k = wn * 32 + nt * 8 + 2 * tig;
        const float as0 = s_asum[k], as1 = s_asum[k + 1];
        float2 cv0 = *(const float2*)(centers + (size_t)dr0 * KK + k);
        float2 o0  = make_float2(c[nt][0] - cv0.x * as0, c[nt][1] - cv0.y * as1);
        *(float2*)(g_vlad + ((size_t)b * DD + dr0) * KK + k) = o0;
        float2 cv1 = *(const float2*)(centers + (size_t)dr1 * KK + k);
        float2 o1  = make_float2(c[nt][2] - cv1.x * as0, c[nt][3] - cv1.y * as1);
        *(float2*)(g_vlad + ((size_t)b * DD + dr1) * KK + k) = o1;
    }
}

// ---------------------------------------------------------------------------
// K3: intra-normalize over D per (b,k), then global L2 normalize per b.
// ---------------------------------------------------------------------------
__global__ void __launch_bounds__(256)
k3_normalize(float* __restrict__ out) {
    const int b   = blockIdx.x;
    const int tid = threadIdx.x;
    const int k   = tid & 63;
    const int ds  = tid >> 6;

    const float* vb = g_vlad + (size_t)b * DD * KK;

    float ss = 0.f;
    for (int d = ds; d < DD; d += 4) {
        float v = vb[(size_t)d * KK + k];
        ss = fmaf(v, v, ss);
    }

    __shared__ float red[4][KK];
    __shared__ float invk[KK];
    __shared__ float ginv;

    red[ds][k] = ss;
    __syncthreads();
    if (tid < KK) {
        float t = red[0][tid] + red[1][tid] + red[2][tid] + red[3][tid];
        float nrm = fmaxf(sqrtf(t), 1e-12f);
        float iv = 1.f / nrm;
        invk[tid] = iv;
        red[0][tid] = t * iv * iv;
    }
    __syncthreads();
    if (tid == 0) {
        float gsum = 0.f;
        for (int i = 0; i < KK; i++) gsum += red[0][i];
        ginv = 1.f / fmaxf(sqrtf(gsum), 1e-12f);
    }
    __syncthreads();

    const float gi = ginv;
    float* ob = out + (size_t)b * DD * KK;
    for (int d = ds; d < DD; d += 4)
        ob[(size_t)d * KK + k] = vb[(size_t)d * KK + k] * invk[k] * gi;
}

// ---------------------------------------------------------------------------
extern "C" void kernel_launch(void* const* d_in, const int* in_sizes, int n_in,
                              void* d_out, int out_size) {
    const float* x       = (const float*)d_in[0];  // [32,512,1024]
    const float* conv_w  = (const float*)d_in[1];  // [64,512]
    const float* centers = (const float*)d_in[2];  // [512,64]
    float* out = (float*)d_out;                    // [32, 512*64]

    const int smem1 = 61440;  // K1: A 40960 B + W 20480 B (score overlay 33280 B)
    const int smem2 = 40960;  // K2: A 20480 B + B 20480 B
    cudaFuncSetAttribute(k1_scores, cudaFuncAttributeMaxDynamicSharedMemorySize, smem1);
    cudaFuncSetAttribute(k2_vlad,   cudaFuncAttributeMaxDynamicSharedMemorySize, smem2);

    k1_scores<<<dim3(8, BB), 256, smem1>>>(x, conv_w);
    k2_vlad<<<dim3(8, BB), 256, smem2>>>(x, centers);
    k3_normalize<<<BB, 256>>>(out);
}

// round 6
// speedup vs baseline: 2.1855x; 1.2487x over previous
#include <cuda_runtime.h>
#include <cuda_bf16.h>

#define BB 32
#define DD 512
#define KK 64
#define NNN 1024

typedef unsigned int u32;

// Scratch (__device__ globals; allocation-free rule)
__device__ __align__(16) __nv_bfloat16 g_assign_hi[(size_t)BB * KK * NNN]; // 4 MB
__device__ __align__(16) __nv_bfloat16 g_assign_lo[(size_t)BB * KK * NNN]; // 4 MB
__device__ __align__(16) float g_asum_part[(size_t)BB * 8 * KK];
__device__ __align__(16) float g_vlad[(size_t)BB * DD * KK];               // 4 MB

// ---------------- helpers ----------------
__device__ __forceinline__ u32 smem_u32(const void* p) {
    u32 a;
    asm("{ .reg .u64 t; cvta.to.shared.u64 t, %1; cvt.u32.u64 %0, t; }" : "=r"(a) : "l"(p));
    return a;
}
__device__ __forceinline__ u32 pack_bf2(float a, float b) {
    __nv_bfloat162 p(__float2bfloat16_rn(a), __float2bfloat16_rn(b));
    return *reinterpret_cast<u32*>(&p);
}
__device__ __forceinline__ u32 split_pack(float a, float b, float& la, float& lb) {
    __nv_bfloat16 ha = __float2bfloat16_rn(a);
    __nv_bfloat16 hb = __float2bfloat16_rn(b);
    la = a - __bfloat162float(ha);
    lb = b - __bfloat162float(hb);
    __nv_bfloat162 p(ha, hb);
    return *reinterpret_cast<u32*>(&p);
}
__device__ __forceinline__ void mma16816(float* c, const u32* a, u32 b0, u32 b1) {
    asm volatile(
        "mma.sync.aligned.m16n8k16.row.col.f32.bf16.bf16.f32 "
        "{%0,%1,%2,%3},{%4,%5,%6,%7},{%8,%9},{%0,%1,%2,%3};"
        : "+f"(c[0]), "+f"(c[1]), "+f"(c[2]), "+f"(c[3])
        : "r"(a[0]), "r"(a[1]), "r"(a[2]), "r"(a[3]), "r"(b0), "r"(b1));
}
__device__ __forceinline__ void ldsm4(u32* r, u32 a) {
    asm volatile("ldmatrix.sync.aligned.m8n8.x4.shared.b16 {%0,%1,%2,%3}, [%4];"
                 : "=r"(r[0]), "=r"(r[1]), "=r"(r[2]), "=r"(r[3]) : "r"(a));
}
__device__ __forceinline__ void ldsm4t(u32* r, u32 a) {
    asm volatile("ldmatrix.sync.aligned.m8n8.x4.trans.shared.b16 {%0,%1,%2,%3}, [%4];"
                 : "=r"(r[0]), "=r"(r[1]), "=r"(r[2]), "=r"(r[3]) : "r"(a));
}
__device__ __forceinline__ void sts128u(u32 a, uint4 v) {
    asm volatile("st.shared.v4.b32 [%0], {%1,%2,%3,%4};"
                 :: "r"(a), "r"(v.x), "r"(v.y), "r"(v.z), "r"(v.w));
}
__device__ __forceinline__ void cvt8(const float* f, uint4& h, uint4& l) {
    u32* hp = (u32*)&h;
    u32* lp = (u32*)&l;
#pragma unroll
    for (int j = 0; j < 4; j++) {
        float la, lb;
        hp[j] = split_pack(f[2 * j], f[2 * j + 1], la, lb);
        lp[j] = pack_bf2(la, lb);
    }
}

// ---------------------------------------------------------------------------
// K1: D[n=128, k=64] = x^T W^T (3-MMA bf16 split). X staged natural [d][n]
// (ldmatrix.x4.trans for A), W staged [k][d] (ldmatrix.x4 for B).
// Fused softmax; writes assign hi/lo bf16 planes (k-major) + asum partials.
// Grid (8, 32), 256 thr, 2 CTA/SM.
// Dyn smem: Xs[2buf][2pl][32 rows x 272B] = 34816; Ws[2][2][64 x 80B] = 20480.
// Score overlay f32[128][65] = 33280 (reuses Xs region).
// ---------------------------------------------------------------------------
__global__ void __launch_bounds__(256, 2)
k1_scores(const float* __restrict__ x, const float* __restrict__ w) {
    extern __shared__ __align__(16) char dyn[];
    float* smf = reinterpret_cast<float*>(dyn);
    const u32 sb = smem_u32(dyn);

    const int tid = threadIdx.x;
    const int b   = blockIdx.y;
    const int n0  = blockIdx.x * 128;
    const float* xb = x + (size_t)b * DD * NNN;

    const int lane = tid & 31, wid = tid >> 5;
    const int wm = wid >> 1, wn = wid & 1;           // warp tile: n rows 32*wm, kc 32*wn
    const int g = lane >> 2, tig = lane & 3;
    const int fr = lane & 7, fi = lane >> 3;

    // A (trans from [d][n]): mat i -> (mh=i&1, kh=i>>1); +mt*32, +ks*4352
    const u32 aoff0 = (u32)((((fi >> 1) * 8) + fr) * 272 + (wm * 32 + (fi & 1) * 8) * 2);
    // B (from [k][d]): mat i -> (tile=i>>1, dh=i&1); +ks*32, second pair +1280
    const u32 boff0 = (u32)((wn * 32 + (fi >> 1) * 8 + fr) * 80 + (fi & 1) * 16);

    // staging roles
    const int sd = tid >> 3, sc = (tid & 7) * 8;     // X: d row, n piece
    const int wk = tid >> 2, wp = (tid & 3) * 8;     // W: k row, d piece

    float c[2][4][4];
#pragma unroll
    for (int i = 0; i < 2; i++)
#pragma unroll
        for (int j = 0; j < 4; j++)
#pragma unroll
            for (int q = 0; q < 4; q++) c[i][j][q] = 0.f;

    float4 xv0, xv1, xv2, xv3, wv0, wv1;
    auto ldC = [&](int dc) {
        const float* p = xb + (size_t)(dc + sd) * NNN + n0 + sc;
        xv0 = *(const float4*)p;
        xv1 = *(const float4*)(p + 4);
        xv2 = *(const float4*)(p + 64);
        xv3 = *(const float4*)(p + 68);
        const float* q = w + (size_t)wk * DD + dc + wp;
        wv0 = *(const float4*)q;
        wv1 = *(const float4*)(q + 4);
    };
    auto stC = [&](int buf) {
        const u32 XH = sb + buf * 17408u, XL = XH + 8704u;
        {
            float f[8] = {xv0.x, xv0.y, xv0.z, xv0.w, xv1.x, xv1.y, xv1.z, xv1.w};
            uint4 h, l;
            cvt8(f, h, l);
            u32 off = (u32)(sd * 272 + sc * 2);
            sts128u(XH + off, h);
            sts128u(XL + off, l);
        }
        {
            float f[8] = {xv2.x, xv2.y, xv2.z, xv2.w, xv3.x, xv3.y, xv3.z, xv3.w};
            uint4 h, l;
            cvt8(f, h, l);
            u32 off = (u32)(sd * 272 + sc * 2 + 128);
            sts128u(XH + off, h);
            sts128u(XL + off, l);
        }
        {
            float f[8] = {wv0.x, wv0.y, wv0.z, wv0.w, wv1.x, wv1.y, wv1.z, wv1.w};
            uint4 h, l;
            cvt8(f, h, l);
            const u32 WH = sb + 34816u + buf * 10240u, WL = WH + 5120u;
            u32 off = (u32)(wk * 80 + wp * 2);
            sts128u(WH + off, h);
            sts128u(WL + off, l);
        }
    };

    ldC(0);
    stC(0);
    __syncthreads();

    for (int ch = 0; ch < 16; ch++) {
        const int buf = ch & 1;
        if (ch < 15) ldC((ch + 1) * 32);
        const u32 XH = sb + buf * 17408u, XL = XH + 8704u;
        const u32 WH = sb + 34816u + buf * 10240u, WL = WH + 5120u;
#pragma unroll
        for (int ks = 0; ks < 2; ks++) {
            u32 bh[8], bl[8];
            ldsm4(bh,     WH + boff0 + ks * 32);
            ldsm4(bh + 4, WH + boff0 + ks * 32 + 1280);
            ldsm4(bl,     WL + boff0 + ks * 32);
            ldsm4(bl + 4, WL + boff0 + ks * 32 + 1280);
            u32 ah[2][4], al[2][4];
#pragma unroll
            for (int mt = 0; mt < 2; mt++) {
                ldsm4t(ah[mt], XH + aoff0 + ks * 4352 + mt * 32);
                ldsm4t(al[mt], XL + aoff0 + ks * 4352 + mt * 32);
            }
#pragma unroll
            for (int mt = 0; mt < 2; mt++)
#pragma unroll
                for (int nt = 0; nt < 4; nt++) {
                    mma16816(c[mt][nt], ah[mt], bh[2 * nt], bh[2 * nt + 1]);
                    mma16816(c[mt][nt], ah[mt], bl[2 * nt], bl[2 * nt + 1]);
                    mma16816(c[mt][nt], al[mt], bh[2 * nt], bh[2 * nt + 1]);
                }
        }
        if (ch < 15) stC(buf ^ 1);
        __syncthreads();
    }

    // scores -> smem overlay [128][65] f32
#pragma unroll
    for (int mt = 0; mt < 2; mt++) {
        const int r0 = wm * 32 + mt * 16 + g;
#pragma unroll
        for (int nt = 0; nt < 4; nt++) {
            const int col = wn * 32 + nt * 8 + 2 * tig;
            smf[r0 * 65 + col]           = c[mt][nt][0];
            smf[r0 * 65 + col + 1]       = c[mt][nt][1];
            smf[(r0 + 8) * 65 + col]     = c[mt][nt][2];
            smf[(r0 + 8) * 65 + col + 1] = c[mt][nt][3];
        }
    }
    __syncthreads();

    // softmax over k per n-row
    if (tid < 128) {
        float r[64];
#pragma unroll
        for (int i = 0; i < 64; i++) r[i] = smf[tid * 65 + i];
        float mx = r[0];
#pragma unroll
        for (int i = 1; i < 64; i++) mx = fmaxf(mx, r[i]);
        float s = 0.f;
#pragma unroll
        for (int i = 0; i < 64; i++) { r[i] = __expf(r[i] - mx); s += r[i]; }
        const float is = 1.f / s;
#pragma unroll
        for (int i = 0; i < 64; i++) smf[tid * 65 + i] = r[i] * is;
    }
    __syncthreads();

    if (tid < 64) {  // asum partial for this n-tile
        float s = 0.f;
        for (int rw = 0; rw < 128; rw++) s += smf[rw * 65 + tid];
        g_asum_part[((size_t)b * 8 + blockIdx.x) * KK + tid] = s;
    }
    {   // assign -> bf16 hi/lo planes, k-major
        const int k  = tid >> 2;
        const int ns = (tid & 3) * 32;
        __nv_bfloat16* oh = g_assign_hi + ((size_t)b * KK + k) * NNN + n0 + ns;
        __nv_bfloat16* ol = g_assign_lo + ((size_t)b * KK + k) * NNN + n0 + ns;
#pragma unroll
        for (int j = 0; j < 32; j += 2) {
            float a0 = smf[(ns + j) * 65 + k];
            float a1 = smf[(ns + j + 1) * 65 + k];
            float la, lb;
            u32 hp = split_pack(a0, a1, la, lb);
            u32 lp = pack_bf2(la, lb);
            *reinterpret_cast<u32*>(oh + j) = hp;
            *reinterpret_cast<u32*>(ol + j) = lp;
        }
    }
}

// ---------------------------------------------------------------------------
// K2: D[d=128, k=64] = x · assign^T over n=1024 (3-MMA split), fused
//     "- centers * asum" epilogue. Grid (4, 32) = 128 CTAs = 1 wave.
// Dyn smem: As[2buf][2pl][128 x 80B] = 40960; Bs[2][2][64 x 80B] = 20480.
// ---------------------------------------------------------------------------
__global__ void __launch_bounds__(256, 1)
k2_vlad(const float* __restrict__ x, const float* __restrict__ centers) {
    extern __shared__ __align__(16) char dyn[];
    __shared__ float s_asum[KK];
    const u32 sb = smem_u32(dyn);

    const int tid = threadIdx.x;
    const int b   = blockIdx.y;
    const int d0  = blockIdx.x * 128;

    const int lane = tid & 31, wid = tid >> 5;
    const int wm = wid >> 1, wn = wid & 1;        // d rows 32*wm, kc 32*wn
    const int g = lane >> 2, tig = lane & 3;
    const int fr = lane & 7, fi = lane >> 3;

    // A (non-trans from [d][n]): +mt*1280, +ks*32
    const u32 aoff0 = (u32)((wm * 32 + (fi & 1) * 8 + fr) * 80 + ((fi >> 1) * 8) * 2);
    // B (non-trans from [kc][n]): +ks*32, second pair +1280
    const u32 boff0 = (u32)((wn * 32 + (fi >> 1) * 8 + fr) * 80 + (fi & 1) * 16);

    const int sd = tid >> 1, sp = (tid & 1) * 16;  // x rows 0..127, 16-el piece
    const int bk = tid >> 2, bp = (tid & 3) * 8;   // assign rows, 8-el piece

    if (tid < 64) {
        float s = 0.f;
#pragma unroll
        for (int q = 0; q < 8; q++) s += g_asum_part[((size_t)b * 8 + q) * KK + tid];
        s_asum[tid] = s;
    }

    const float* xb = x + (size_t)b * DD * NNN;
    const __nv_bfloat16* ahp = g_assign_hi + ((size_t)b * KK + bk) * NNN;
    const __nv_bfloat16* alp = g_assign_lo + ((size_t)b * KK + bk) * NNN;

    float c[2][4][4];
#pragma unroll
    for (int i = 0; i < 2; i++)
#pragma unroll
        for (int j = 0; j < 4; j++)
#pragma unroll
            for (int q = 0; q < 4; q++) c[i][j][q] = 0.f;

    float4 xv0, xv1, xv2, xv3;
    uint4 bhv, blv;
    auto ldC = [&](int nb) {
        const float* p = xb + (size_t)(d0 + sd) * NNN + nb + sp;
        xv0 = *(const float4*)p;
        xv1 = *(const float4*)(p + 4);
        xv2 = *(const float4*)(p + 8);
        xv3 = *(const float4*)(p + 12);
        bhv = *(const uint4*)(ahp + nb + bp);
        blv = *(const uint4*)(alp + nb + bp);
    };
    auto stC = [&](int buf) {
        const u32 AH = sb + buf * 20480u, AL = AH + 10240u;
        {
            float f[8] = {xv0.x, xv0.y, xv0.z, xv0.w, xv1.x, xv1.y, xv1.z, xv1.w};
            uint4 h, l;
            cvt8(f, h, l);
            u32 off = (u32)(sd * 80 + sp * 2);
            sts128u(AH + off, h);
            sts128u(AL + off, l);
        }
        {
            float f[8] = {xv2.x, xv2.y, xv2.z, xv2.w, xv3.x, xv3.y, xv3.z, xv3.w};
            uint4 h, l;
            cvt8(f, h, l);
            u32 off = (u32)(sd * 80 + sp * 2 + 16);
            sts128u(AH + off, h);
            sts128u(AL + off, l);
        }
        const u32 BH = sb + 40960u + buf * 10240u, BL = BH + 5120u;
        u32 boff = (u32)(bk * 80 + bp * 2);
        sts128u(BH + boff, bhv);
        sts128u(BL + boff, blv);
    };

    ldC(0);
    stC(0);
    __syncthreads();

    for (int ch = 0; ch < 32; ch++) {
        const int buf = ch & 1;
        if (ch < 31) ldC((ch + 1) * 32);
        const u32 AH = sb + buf * 20480u, AL = AH + 10240u;
        const u32 BH = sb + 40960u + buf * 10240u, BL = BH + 5120u;
#pragma unroll
        for (int ks = 0; ks < 2; ks++) {
            u32 bh[8], bl[8];
            ldsm4(bh,     BH + boff0 + ks * 32);
            ldsm4(bh + 4, BH + boff0 + ks * 32 + 1280);
            ldsm4(bl,     BL + boff0 + ks * 32);
            ldsm4(bl + 4, BL + boff0 + ks * 32 + 1280);
            u32 ah[2][4], al[2][4];
#pragma unroll
            for (int mt = 0; mt < 2; mt++) {
                ldsm4(ah[mt], AH + aoff0 + ks * 32 + mt * 1280);
                ldsm4(al[mt], AL + aoff0 + ks * 32 + mt * 1280);
            }
#pragma unroll
            for (int mt = 0; mt < 2; mt++)
#pragma unroll
                for (int nt = 0; nt < 4; nt++) {
                    mma16816(c[mt][nt], ah[mt], bh[2 * nt], bh[2 * nt + 1]);
                    mma16816(c[mt][nt], ah[mt], bl[2 * nt], bl[2 * nt + 1]);
                    mma16816(c[mt][nt], al[mt], bh[2 * nt], bh[2 * nt + 1]);
                }
        }
        if (ch < 31) stC(buf ^ 1);
        __syncthreads();
    }

    // epilogue: vlad[d][k] = D - centers[d][k] * asum[k]
#pragma unroll
    for (int mt = 0; mt < 2; mt++) {
        const int dr0 = d0 + wm * 32 + mt * 16 + g;
        const int dr1 = dr0 + 8;
#pragma unroll
        for (int nt = 0; nt < 4; nt++) {
            const int k = wn * 32 + nt * 8 + 2 * tig;
            const float as0 = s_asum[k], as1 = s_asum[k + 1];
            float2 cv0 = *(const float2*)(centers + (size_t)dr0 * KK + k);
            float2 o0  = make_float2(c[mt][nt][0] - cv0.x * as0,
                                     c[mt][nt][1] - cv0.y * as1);
            *(float2*)(g_vlad + ((size_t)b * DD + dr0) * KK + k) = o0;
            float2 cv1 = *(const float2*)(centers + (size_t)dr1 * KK + k);
            float2 o1  = make_float2(c[mt][nt][2] - cv1.x * as0,
                                     c[mt][nt][3] - cv1.y * as1);
            *(float2*)(g_vlad + ((size_t)b * DD + dr1) * KK + k) = o1;
        }
    }
}

// ---------------------------------------------------------------------------
// K3: intra-normalize over D per (b,k), then global L2 normalize per b.
// ---------------------------------------------------------------------------
__global__ void __launch_bounds__(256)
k3_normalize(float* __restrict__ out) {
    const int b   = blockIdx.x;
    const int tid = threadIdx.x;
    const int k   = tid & 63;
    const int ds  = tid >> 6;

    const float* vb = g_vlad + (size_t)b * DD * KK;

    float ss = 0.f;
    for (int d = ds; d < DD; d += 4) {
        float v = vb[(size_t)d * KK + k];
        ss = fmaf(v, v, ss);
    }

    __shared__ float red[4][KK];
    __shared__ float invk[KK];
    __shared__ float ginv;

    red[ds][k] = ss;
    __syncthreads();
    if (tid < KK) {
        float t = red[0][tid] + red[1][tid] + red[2][tid] + red[3][tid];
        float nrm = fmaxf(sqrtf(t), 1e-12f);
        float iv = 1.f / nrm;
        invk[tid] = iv;
        red[0][tid] = t * iv * iv;
    }
    __syncthreads();
    if (tid == 0) {
        float gsum = 0.f;
        for (int i = 0; i < KK; i++) gsum += red[0][i];
        ginv = 1.f / fmaxf(sqrtf(gsum), 1e-12f);
    }
    __syncthreads();

    const float gi = ginv;
    float* ob = out + (size_t)b * DD * KK;
    for (int d = ds; d < DD; d += 4)
        ob[(size_t)d * KK + k] = vb[(size_t)d * KK + k] * invk[k] * gi;
}

// ---------------------------------------------------------------------------
extern "C" void kernel_launch(void* const* d_in, const int* in_sizes, int n_in,
                              void* d_out, int out_size) {
    const float* x       = (const float*)d_in[0];  // [32,512,1024]
    const float* conv_w  = (const float*)d_in[1];  // [64,512]
    const float* centers = (const float*)d_in[2];  // [512,64]
    float* out = (float*)d_out;                    // [32, 512*64]

    const int smem1 = 55296;
    const int smem2 = 61440;
    cudaFuncSetAttribute(k1_scores, cudaFuncAttributeMaxDynamicSharedMemorySize, smem1);
    cudaFuncSetAttribute(k2_vlad,   cudaFuncAttributeMaxDynamicSharedMemorySize, smem2);

    k1_scores<<<dim3(8, BB), 256, smem1>>>(x, conv_w);
    k2_vlad<<<dim3(4, BB), 256, smem2>>>(x, centers);
    k3_normalize<<<BB, 256>>>(out);
}